// round 13
// baseline (speedup 1.0000x reference)
#include <cuda_runtime.h>
#include <cuda_bf16.h>
#include <cstdint>

// Problem constants
#define BB 2
#define TT 2048
#define CC 1024
#define HH 16
#define DD 64
#define MMr (BB*TT)          // 4096

// ---------------- scratch (device globals; no allocation allowed) ----------
__device__ __nv_bfloat16 g_xh[MMr*CC];
__device__ __nv_bfloat16 g_xl[MMr*CC];
__device__ __nv_bfloat16 g_ah[MMr*CC];      // attn output hi [b,t,c]
__device__ __nv_bfloat16 g_al[MMr*CC];      // attn output lo
__device__ __nv_bfloat16 g_wth[4*CC*CC];    // W^T hi, [n][k], 4 matrices
__device__ __nv_bfloat16 g_wtl[4*CC*CC];    // W^T lo
__device__ __nv_bfloat16 g_qh[BB*HH*TT*DD]; // [b,h,t,d] (pre-scaled by log2e/8)
__device__ __nv_bfloat16 g_ql[BB*HH*TT*DD];
__device__ __nv_bfloat16 g_kh[BB*HH*TT*DD]; // [b,h,t,d]
__device__ __nv_bfloat16 g_kl[BB*HH*TT*DD];
__device__ __nv_bfloat16 g_vth[BB*HH*DD*TT]; // V^T [b,h,d,t]
__device__ __nv_bfloat16 g_vtl[BB*HH*DD*TT];

// ---------------- helpers ---------------------------------------------------
__device__ __forceinline__ uint32_t smem_u32(const void* p) {
    uint32_t a;
    asm("{ .reg .u64 t; cvta.to.shared.u64 t, %1; cvt.u32.u64 %0, t; }"
        : "=r"(a) : "l"(p));
    return a;
}

#define CP_ASYNC16(s, g) \
    asm volatile("cp.async.cg.shared.global [%0], [%1], 16;" :: "r"(s), "l"(g) : "memory")
#define CP_COMMIT()  asm volatile("cp.async.commit_group;" ::: "memory")
#define CP_WAIT(n)   asm volatile("cp.async.wait_group %0;" :: "n"(n) : "memory")

__device__ __forceinline__ void ldmx4(uint32_t* r, uint32_t addr) {
    asm volatile("ldmatrix.sync.aligned.m8n8.x4.shared.b16 {%0,%1,%2,%3}, [%4];"
        : "=r"(r[0]), "=r"(r[1]), "=r"(r[2]), "=r"(r[3]) : "r"(addr));
}
__device__ __forceinline__ void mma16816(float* c, const uint32_t* a, const uint32_t* b) {
    asm volatile(
        "mma.sync.aligned.m16n8k16.row.col.f32.bf16.bf16.f32 "
        "{%0,%1,%2,%3}, {%4,%5,%6,%7}, {%8,%9}, {%0,%1,%2,%3};"
        : "+f"(c[0]), "+f"(c[1]), "+f"(c[2]), "+f"(c[3])
        : "r"(a[0]), "r"(a[1]), "r"(a[2]), "r"(a[3]), "r"(b[0]), "r"(b[1]));
}
// raw MUFU exp2 (inputs finite, <= 0 in our use; approx err ~2^-22)
__device__ __forceinline__ float ex2(float x) {
    float y;
    asm("ex2.approx.ftz.f32 %0, %1;" : "=f"(y) : "f"(x));
    return y;
}
// pack (c0 -> low, c1 -> high) as bf16x2 (hi) plus residual pair (lo)
__device__ __forceinline__ void split2(float c0, float c1, uint32_t& h, uint32_t& l) {
    const __nv_bfloat16 b0 = __float2bfloat16(c0);
    const __nv_bfloat16 b1 = __float2bfloat16(c1);
    asm("cvt.rn.bf16x2.f32 %0, %1, %2;" : "=r"(h) : "f"(c1), "f"(c0));
    const float r0 = c0 - __bfloat162float(b0);
    const float r1 = c1 - __bfloat162float(b1);
    asm("cvt.rn.bf16x2.f32 %0, %1, %2;" : "=r"(l) : "f"(r1), "f"(r0));
}

// ---------------------------------------------------------------------------
// bf16 HMMA split GEMM, fused passes, single-sync pipeline, 2 CTAs/SM.
// MMA issue is pass-major over mt: each accumulator revisited at distance 4
// (was 2) to cover mma.sync latency.
// ---------------------------------------------------------------------------
#define SAB 80                       // smem row stride, bytes (40 halves)
#define T_BYTES (128*SAB)            // one 128x32 bf16 tile: 10240 B
#define STAGE_BYTES (4*T_BYTES)      // Ah, Al, Bh, Bl: 40960 B
#define NS 2
#define GEMM_SMEM (NS*STAGE_BYTES)   // 81920 B
#define NITER 32                     // 1024/32
#define SCQ 0.18033688011112042f     // (1/8) * log2(e)

template<int MODE>
__global__ __launch_bounds__(256, 2)
void gemm_tc(const __nv_bfloat16* __restrict__ Ah,
             const __nv_bfloat16* __restrict__ Al,
             float* __restrict__ outp,
             const float* __restrict__ bias0,
             const float* __restrict__ bias1,
             const float* __restrict__ bias2)
{
    extern __shared__ __align__(128) char dsm[];

    const int tid    = threadIdx.x;
    const int wid    = tid >> 5;
    const int lane   = tid & 31;
    const int warp_m = wid & 3;
    const int warp_n = wid >> 2;
    const int bn     = blockIdx.x * 128;
    const int bm     = blockIdx.y * 128;
    const int z      = (MODE == 0) ? blockIdx.z : 3;

    const __nv_bfloat16* Bhp = g_wth + (size_t)z * (CC * CC);
    const __nv_bfloat16* Blp = g_wtl + (size_t)z * (CC * CC);
    const float* bias = (MODE == 0) ? ((z == 0) ? bias0 : (z == 1) ? bias1 : bias2) : bias0;

    const uint32_t smem_base = smem_u32(dsm);

    float acc[2][8][4];
    #pragma unroll
    for (int mt = 0; mt < 2; mt++)
        #pragma unroll
        for (int nt = 0; nt < 8; nt++)
            #pragma unroll
            for (int e = 0; e < 4; e++) acc[mt][nt][e] = 0.0f;

    auto load_stage = [&](int L) {
        const int slot = L & (NS - 1);
        const int kt   = L * 32;
        const uint32_t s0 = smem_base + slot * STAGE_BYTES;
        #pragma unroll
        for (int i = 0; i < 2; i++) {
            const int idx = i * 256 + tid;          // 0..511
            const int r = idx >> 2, c = idx & 3;    // row, 16B chunk
            const uint32_t so = r * SAB + c * 16;
            const size_t ga = (size_t)(bm + r) * CC + kt + c * 8;
            const size_t gb = (size_t)(bn + r) * CC + kt + c * 8;
            CP_ASYNC16(s0 + so,               Ah  + ga);
            CP_ASYNC16(s0 + T_BYTES + so,     Al  + ga);
            CP_ASYNC16(s0 + 2*T_BYTES + so,   Bhp + gb);
            CP_ASYNC16(s0 + 3*T_BYTES + so,   Blp + gb);
        }
    };

    load_stage(0); CP_COMMIT();

    for (int it = 0; it < NITER; it++) {
        CP_WAIT(0);
        __syncthreads();
        if (it + 1 < NITER) load_stage(it + 1);
        CP_COMMIT();

        const uint32_t s0 = smem_base + (it & (NS - 1)) * STAGE_BYTES;
        const uint32_t aBase = s0 + (warp_m * 32 + (lane & 15)) * SAB + (lane >> 4) * 16;
        const uint32_t bBase = s0 + 2*T_BYTES
                                  + (warp_n * 64 + (lane & 7) + ((lane >> 4) << 3)) * SAB
                                  + ((lane >> 3) & 1) * 16;
        #pragma unroll
        for (int kk = 0; kk < 2; kk++) {       // k = 0, 16
            uint32_t ah[2][4], al[2][4];
            ldmx4(ah[0], aBase + kk * 32);
            ldmx4(ah[1], aBase + 16 * SAB + kk * 32);
            ldmx4(al[0], aBase + T_BYTES + kk * 32);
            ldmx4(al[1], aBase + T_BYTES + 16 * SAB + kk * 32);
            #pragma unroll
            for (int np = 0; np < 4; np++) {
                uint32_t bh[4], bl[4];
                ldmx4(bh, bBase + np * 16 * SAB + kk * 32);
                ldmx4(bl, bBase + T_BYTES + np * 16 * SAB + kk * 32);
                // pass-major: each acc quad revisited at distance 4
                mma16816(acc[0][np * 2 + 0], ah[0], &bh[0]);
                mma16816(acc[0][np * 2 + 1], ah[0], &bh[2]);
                mma16816(acc[1][np * 2 + 0], ah[1], &bh[0]);
                mma16816(acc[1][np * 2 + 1], ah[1], &bh[2]);
                mma16816(acc[0][np * 2 + 0], ah[0], &bl[0]);
                mma16816(acc[0][np * 2 + 1], ah[0], &bl[2]);
                mma16816(acc[1][np * 2 + 0], ah[1], &bl[0]);
                mma16816(acc[1][np * 2 + 1], ah[1], &bl[2]);
                mma16816(acc[0][np * 2 + 0], al[0], &bh[0]);
                mma16816(acc[0][np * 2 + 1], al[0], &bh[2]);
                mma16816(acc[1][np * 2 + 0], al[1], &bh[0]);
                mma16816(acc[1][np * 2 + 1], al[1], &bh[2]);
            }
        }
    }

    // epilogue
    const int groupID = lane >> 2;
    const int tig     = lane & 3;

    #pragma unroll
    for (int mt = 0; mt < 2; mt++) {
        #pragma unroll
        for (int nt = 0; nt < 8; nt++) {
            const int col = bn + warp_n * 64 + nt * 8 + tig * 2;
            const float b0 = bias[col], b1 = bias[col + 1];
            #pragma unroll
            for (int half = 0; half < 2; half++) {
                const int rg = bm + warp_m * 32 + mt * 16 + groupID + half * 8;
                float vx = acc[mt][nt][half * 2 + 0] + b0;
                float vy = acc[mt][nt][half * 2 + 1] + b1;
                if (MODE == 1) {
                    float2 v; v.x = vx; v.y = vy;
                    *(float2*)&outp[(size_t)rg * CC + col] = v;
                } else {
                    if (z == 0) { vx *= SCQ; vy *= SCQ; }   // pre-scale Q
                    const int b = rg >> 11, t = rg & 2047;
                    const int h = col >> 6, d = col & 63;
                    const __nv_bfloat16 hx = __float2bfloat16(vx);
                    const __nv_bfloat16 hy = __float2bfloat16(vy);
                    const __nv_bfloat16 lx = __float2bfloat16(vx - __bfloat162float(hx));
                    const __nv_bfloat16 ly = __float2bfloat16(vy - __bfloat162float(hy));
                    if (z == 2) {
                        // V^T [b,h,d,t]
                        const size_t a0 = ((size_t)(b * HH + h) * DD + d) * TT + t;
                        g_vth[a0]      = hx;  g_vtl[a0]      = lx;
                        g_vth[a0 + TT] = hy;  g_vtl[a0 + TT] = ly;
                    } else {
                        __nv_bfloat16* dh = (z == 0) ? g_qh : g_kh;
                        __nv_bfloat16* dl = (z == 0) ? g_ql : g_kl;
                        const size_t a0 = ((size_t)(b * HH + h) * TT + t) * DD + d;
                        ushort2 Hu, Lu;
                        Hu.x = __bfloat16_as_ushort(hx); Hu.y = __bfloat16_as_ushort(hy);
                        Lu.x = __bfloat16_as_ushort(lx); Lu.y = __bfloat16_as_ushort(ly);
                        *(ushort2*)&dh[a0] = Hu;
                        *(ushort2*)&dl[a0] = Lu;
                    }
                }
            }
        }
    }
}

// ---------------------------------------------------------------------------
// fp32 -> (hi, lo) bf16 split, vectorized by float4
// ---------------------------------------------------------------------------
__global__ __launch_bounds__(256)
void split_f32(const float4* __restrict__ in, __nv_bfloat16* __restrict__ hi,
               __nv_bfloat16* __restrict__ lo)
{
    const int i = blockIdx.x * 256 + threadIdx.x;
    const float4 v = in[i];
    __nv_bfloat16 h0 = __float2bfloat16(v.x);
    __nv_bfloat16 h1 = __float2bfloat16(v.y);
    __nv_bfloat16 h2 = __float2bfloat16(v.z);
    __nv_bfloat16 h3 = __float2bfloat16(v.w);
    ushort4 H, L;
    H.x = __bfloat16_as_ushort(h0); H.y = __bfloat16_as_ushort(h1);
    H.z = __bfloat16_as_ushort(h2); H.w = __bfloat16_as_ushort(h3);
    L.x = __bfloat16_as_ushort(__float2bfloat16(v.x - __bfloat162float(h0)));
    L.y = __bfloat16_as_ushort(__float2bfloat16(v.y - __bfloat162float(h1)));
    L.z = __bfloat16_as_ushort(__float2bfloat16(v.z - __bfloat162float(h2)));
    L.w = __bfloat16_as_ushort(__float2bfloat16(v.w - __bfloat162float(h3)));
    *(ushort4*)(hi + (size_t)i * 4) = H;
    *(ushort4*)(lo + (size_t)i * 4) = L;
}

// ---------------------------------------------------------------------------
// Transpose + split all 4 weight matrices: W[k][n] fp32 -> Wt hi/lo [n][k] bf16
// ---------------------------------------------------------------------------
__global__ __launch_bounds__(256)
void transpose_split_w(const float* __restrict__ Wq, const float* __restrict__ Wk,
                       const float* __restrict__ Wv, const float* __restrict__ Wo)
{
    __shared__ float tile[32][33];
    const int zz = blockIdx.z;
    const float* W = (zz == 0) ? Wq : (zz == 1) ? Wk : (zz == 2) ? Wv : Wo;
    const int tx = threadIdx.x, ty = threadIdx.y;
    const int n0 = blockIdx.x * 32;
    const int k0 = blockIdx.y * 32;
    #pragma unroll
    for (int i = ty; i < 32; i += 8)
        tile[i][tx] = W[(size_t)(k0 + i) * CC + n0 + tx];
    __syncthreads();
    __nv_bfloat16* oh = g_wth + (size_t)zz * (CC * CC);
    __nv_bfloat16* ol = g_wtl + (size_t)zz * (CC * CC);
    #pragma unroll
    for (int i = ty; i < 32; i += 8) {
        const float v = tile[tx][i];
        const __nv_bfloat16 h = __float2bfloat16(v);
        oh[(size_t)(n0 + i) * CC + k0 + tx] = h;
        ol[(size_t)(n0 + i) * CC + k0 + tx] = __float2bfloat16(v - __bfloat162float(h));
    }
}

// ---------------------------------------------------------------------------
// HMMA flash-attention, causal, fused passes, 2 CTAs/SM.
// S and PV MMA issue is np-paired pass-major: accumulators revisited at
// distance 4 to cover mma.sync latency.
// ---------------------------------------------------------------------------
#define SKB 144                       // smem row stride bytes (64 halves + pad)
#define KTB (64*SKB)                  // one 64x64 bf16 tile: 9216 B
#define QREG (4*KTB)                  // Qh + Ql: 36864 B
#define ATT_STAGE (4*KTB)             // Kh,Kl,Vth,Vtl: 36864 B
#define ATT_SMEM (QREG + 2*ATT_STAGE) // 110592 B

__global__ __launch_bounds__(256, 2)
void attn_mma()
{
    extern __shared__ __align__(128) char dsm[];
    const int tid  = threadIdx.x;
    const int wid  = tid >> 5;
    const int lane = tid & 31;
    const int g    = lane >> 2;
    const int tig  = lane & 3;
    const int qb   = (int)gridDim.x - 1 - (int)blockIdx.x;   // long blocks first
    const int bh   = blockIdx.y;
    const int bI   = bh >> 4;
    const int hd   = bh & 15;
    const uint32_t sbase = smem_u32(dsm);
    const uint32_t kvbase = sbase + QREG;

    // ---- stage Q (hi/lo) into persistent region [Qh | Ql] ----
    {
        const size_t qoff = ((size_t)bh * TT + (size_t)qb * 128) * DD;
        #pragma unroll
        for (int i = 0; i < 4; i++) {
            const int idx = i * 256 + tid;           // 0..1023
            const int r = idx >> 3, c = idx & 7;
            CP_ASYNC16(sbase + r * SKB + c * 16,         g_qh + qoff + (size_t)r * DD + c * 8);
            CP_ASYNC16(sbase + 2*KTB + r * SKB + c * 16, g_ql + qoff + (size_t)r * DD + c * 8);
        }
    }

    float c_o[8][4];
    #pragma unroll
    for (int nt = 0; nt < 8; nt++)
        #pragma unroll
        for (int e = 0; e < 4; e++) c_o[nt][e] = 0.0f;
    float mI[2] = {-1e30f, -1e30f}, lI[2] = {0.0f, 0.0f};

    auto load_kv = [&](int j) {
        const uint32_t sb = kvbase + (j & 1) * ATT_STAGE;
        #pragma unroll
        for (int i = 0; i < 2; i++) {
            const int idx = i * 256 + tid;           // 0..511
            const int r = idx >> 3, c = idx & 7;
            const size_t gk = ((size_t)bh * TT + j * 64 + r) * DD + c * 8;
            CP_ASYNC16(sb + r * SKB + c * 16,       g_kh + gk);
            CP_ASYNC16(sb + KTB + r * SKB + c * 16, g_kl + gk);
            const size_t gv = ((size_t)bh * DD + r) * TT + j * 64 + c * 8;
            CP_ASYNC16(sb + 2*KTB + r * SKB + c * 16, g_vth + gv);
            CP_ASYNC16(sb + 3*KTB + r * SKB + c * 16, g_vtl + gv);
        }
    };

    CP_COMMIT();                 // group: Q
    const int ntiles = 2 * qb + 2;
    load_kv(0); CP_COMMIT();     // group: kv0

    const uint32_t qB = sbase + (wid * 16 + (lane & 15)) * SKB + (lane >> 4) * 16;

    for (int j = 0; j < ntiles; j++) {
        CP_WAIT(0);                // tile j (and Q) arrived
        __syncthreads();           // all warps done with tile j-1 (slot gets overwritten)
        if (j + 1 < ntiles) load_kv(j + 1);
        CP_COMMIT();

        const uint32_t sb = kvbase + (j & 1) * ATT_STAGE;
        const uint32_t bB = sb + ((lane & 7) + ((lane >> 4) << 3)) * SKB
                               + ((lane >> 3) & 1) * 16;

        // ---- S = Q K^T (fused 3 passes; np-paired, pass-major) ----
        float c_s[8][4];
        #pragma unroll
        for (int nt = 0; nt < 8; nt++)
            #pragma unroll
            for (int e = 0; e < 4; e++) c_s[nt][e] = 0.0f;

        #pragma unroll
        for (int kk = 0; kk < 4; kk++) {
            uint32_t qh_[4], ql_[4];
            ldmx4(qh_, qB + kk * 32);
            ldmx4(ql_, qB + 2*KTB + kk * 32);
            #pragma unroll
            for (int np2 = 0; np2 < 4; np2 += 2) {
                uint32_t bh0[4], bh1[4], bl0[4], bl1[4];
                ldmx4(bh0, bB + np2 * 16 * SKB + kk * 32);
                ldmx4(bh1, bB + (np2 + 1) * 16 * SKB + kk * 32);
                ldmx4(bl0, bB + KTB + np2 * 16 * SKB + kk * 32);
                ldmx4(bl1, bB + KTB + (np2 + 1) * 16 * SKB + kk * 32);
                float* a0 = c_s[np2 * 2 + 0];
                float* a1 = c_s[np2 * 2 + 1];
                float* a2 = c_s[np2 * 2 + 2];
                float* a3 = c_s[np2 * 2 + 3];
                mma16816(a0, qh_, &bh0[0]);
                mma16816(a1, qh_, &bh0[2]);
                mma16816(a2, qh_, &bh1[0]);
                mma16816(a3, qh_, &bh1[2]);
                mma16816(a0, qh_, &bl0[0]);
                mma16816(a1, qh_, &bl0[2]);
                mma16816(a2, qh_, &bl1[0]);
                mma16816(a3, qh_, &bl1[2]);
                mma16816(a0, ql_, &bh0[0]);
                mma16816(a1, ql_, &bh0[2]);
                mma16816(a2, ql_, &bh1[0]);
                mma16816(a3, ql_, &bh1[2]);
            }
        }

        // ---- causal mask (only on the 2 diagonal tiles; uniform branch) ----
        if (j >= 2 * qb) {
            const int jbase = j * 64;
            #pragma unroll
            for (int hh = 0; hh < 2; hh++) {
                const int qrow = qb * 128 + wid * 16 + g + hh * 8;
                #pragma unroll
                for (int nt = 0; nt < 8; nt++)
                    #pragma unroll
                    for (int e = 0; e < 2; e++) {
                        const int col = jbase + nt * 8 + tig * 2 + e;
                        if (col > qrow) c_s[nt][hh * 2 + e] = -1e30f;
                    }
            }
        }

        // ---- online softmax (values already in exp2 domain) ----
        #pragma unroll
        for (int hh = 0; hh < 2; hh++) {
            float mx = -1e30f;
            #pragma unroll
            for (int nt = 0; nt < 8; nt++) {
                mx = fmaxf(mx, c_s[nt][hh * 2 + 0]);
                mx = fmaxf(mx, c_s[nt][hh * 2 + 1]);
            }
            mx = fmaxf(mx, __shfl_xor_sync(0xffffffffu, mx, 1));
            mx = fmaxf(mx, __shfl_xor_sync(0xffffffffu, mx, 2));
            const float mN = fmaxf(mI[hh], mx);
            const float corr = ex2(mI[hh] - mN);
            mI[hh] = mN;
            float rs = 0.0f;
            #pragma unroll
            for (int nt = 0; nt < 8; nt++)
                #pragma unroll
                for (int e = 0; e < 2; e++) {
                    const float p = ex2(c_s[nt][hh * 2 + e] - mN);
                    c_s[nt][hh * 2 + e] = p;
                    rs += p;
                }
            rs += __shfl_xor_sync(0xffffffffu, rs, 1);
            rs += __shfl_xor_sync(0xffffffffu, rs, 2);
            lI[hh] = lI[hh] * corr + rs;
            #pragma unroll
            for (int nt = 0; nt < 8; nt++) {
                c_o[nt][hh * 2 + 0] *= corr;
                c_o[nt][hh * 2 + 1] *= corr;
            }
        }

        // ---- re-pack P as A fragments (hi/lo) ----
        uint32_t phf[4][4], plf[4][4];
        #pragma unroll
        for (int kk = 0; kk < 4; kk++) {
            split2(c_s[2*kk][0],   c_s[2*kk][1],   phf[kk][0], plf[kk][0]);
            split2(c_s[2*kk][2],   c_s[2*kk][3],   phf[kk][1], plf[kk][1]);
            split2(c_s[2*kk+1][0], c_s[2*kk+1][1], phf[kk][2], plf[kk][2]);
            split2(c_s[2*kk+1][2], c_s[2*kk+1][3], phf[kk][3], plf[kk][3]);
        }

        // ---- O += P V (fused 3 passes; np-paired, pass-major) ----
        const uint32_t vB = bB + 2 * KTB;
        #pragma unroll
        for (int kk = 0; kk < 4; kk++) {
            #pragma unroll
            for (int np2 = 0; np2 < 4; np2 += 2) {
                uint32_t vh0[4], vh1[4], vl0[4], vl1[4];
                ldmx4(vh0, vB + np2 * 16 * SKB + kk * 32);
                ldmx4(vh1, vB + (np2 + 1) * 16 * SKB + kk * 32);
                ldmx4(vl0, vB + KTB + np2 * 16 * SKB + kk * 32);
                ldmx4(vl1, vB + KTB + (np2 + 1) * 16 * SKB + kk * 32);
                float* a0 = c_o[np2 * 2 + 0];
                float* a1 = c_o[np2 * 2 + 1];
                float* a2 = c_o[np2 * 2 + 2];
                float* a3 = c_o[np2 * 2 + 3];
                mma16816(a0, phf[kk], &vh0[0]);
                mma16816(a1, phf[kk], &vh0[2]);
                mma16816(a2, phf[kk], &vh1[0]);
                mma16816(a3, phf[kk], &vh1[2]);
                mma16816(a0, phf[kk], &vl0[0]);
                mma16816(a1, phf[kk], &vl0[2]);
                mma16816(a2, phf[kk], &vl1[0]);
                mma16816(a3, phf[kk], &vl1[2]);
                mma16816(a0, plf[kk], &vh0[0]);
                mma16816(a1, plf[kk], &vh0[2]);
                mma16816(a2, plf[kk], &vh1[0]);
                mma16816(a3, plf[kk], &vh1[2]);
            }
        }
    }

    // ---- epilogue: O/l -> bf16 hi/lo into g_ah/g_al [b,t,c] ----
    #pragma unroll
    for (int hh = 0; hh < 2; hh++) {
        const float inv = 1.0f / lI[hh];
        const int t = qb * 128 + wid * 16 + g + hh * 8;
        const size_t rowb = ((size_t)bI * TT + t) * CC + hd * 64;
        #pragma unroll
        for (int nt = 0; nt < 8; nt++) {
            const float v0 = c_o[nt][hh * 2 + 0] * inv;
            const float v1 = c_o[nt][hh * 2 + 1] * inv;
            const __nv_bfloat16 h0 = __float2bfloat16(v0);
            const __nv_bfloat16 h1 = __float2bfloat16(v1);
            ushort2 Hu, Lu;
            Hu.x = __bfloat16_as_ushort(h0);
            Hu.y = __bfloat16_as_ushort(h1);
            Lu.x = __bfloat16_as_ushort(__float2bfloat16(v0 - __bfloat162float(h0)));
            Lu.y = __bfloat16_as_ushort(__float2bfloat16(v1 - __bfloat162float(h1)));
            const size_t a0 = rowb + nt * 8 + tig * 2;
            *(ushort2*)&g_ah[a0] = Hu;
            *(ushort2*)&g_al[a0] = Lu;
        }
    }
}

// ---------------------------------------------------------------------------
extern "C" void kernel_launch(void* const* d_in, const int* in_sizes, int n_in,
                              void* d_out, int out_size)
{
    const float* x  = (const float*)d_in[0];
    const float* Wq = (const float*)d_in[1];
    const float* bq = (const float*)d_in[2];
    const float* Wk = (const float*)d_in[3];
    const float* bk = (const float*)d_in[4];
    const float* Wv = (const float*)d_in[5];
    const float* bv = (const float*)d_in[6];
    const float* Wo = (const float*)d_in[7];
    const float* bo = (const float*)d_in[8];
    float* out = (float*)d_out;

    cudaFuncSetAttribute(gemm_tc<0>, cudaFuncAttributeMaxDynamicSharedMemorySize, GEMM_SMEM);
    cudaFuncSetAttribute(gemm_tc<1>, cudaFuncAttributeMaxDynamicSharedMemorySize, GEMM_SMEM);
    cudaFuncSetAttribute(attn_mma,   cudaFuncAttributeMaxDynamicSharedMemorySize, ATT_SMEM);

    __nv_bfloat16 *xh, *xl, *ah, *al;
    cudaGetSymbolAddress((void**)&xh, g_xh);
    cudaGetSymbolAddress((void**)&xl, g_xl);
    cudaGetSymbolAddress((void**)&ah, g_ah);
    cudaGetSymbolAddress((void**)&al, g_al);

    // split x into bf16 hi/lo, transpose+split all weights
    split_f32<<<MMr * CC / 1024, 256>>>((const float4*)x, xh, xl);
    transpose_split_w<<<dim3(32, 32, 4), dim3(32, 8)>>>(Wq, Wk, Wv, Wo);

    // QKV projections (HMMA) -> bf16 hi/lo Q/K/V^T (Q pre-scaled)
    gemm_tc<0><<<dim3(8, 32, 3), 256, GEMM_SMEM>>>(xh, xl, nullptr, bq, bk, bv);

    // attention (HMMA) -> bf16 hi/lo attn output
    attn_mma<<<dim3(16, 32), 256, ATT_SMEM>>>();

    // output projection (HMMA)
    gemm_tc<1><<<dim3(8, 32, 1), 256, GEMM_SMEM>>>(ah, al, out, bo, bo, bo);
}

// round 14
// speedup vs baseline: 1.0038x; 1.0038x over previous
#include <cuda_runtime.h>
#include <cuda_bf16.h>
#include <cstdint>

// Problem constants
#define BB 2
#define TT 2048
#define CC 1024
#define HH 16
#define DD 64
#define MMr (BB*TT)          // 4096

// ---------------- scratch (device globals; no allocation allowed) ----------
__device__ __nv_bfloat16 g_xh[MMr*CC];
__device__ __nv_bfloat16 g_xl[MMr*CC];
__device__ __nv_bfloat16 g_ah[MMr*CC];      // attn output hi [b,t,c]
__device__ __nv_bfloat16 g_al[MMr*CC];      // attn output lo
__device__ __nv_bfloat16 g_wth[4*CC*CC];    // W^T hi, [n][k], 4 matrices
__device__ __nv_bfloat16 g_wtl[4*CC*CC];    // W^T lo
__device__ __nv_bfloat16 g_qh[BB*HH*TT*DD]; // [b,h,t,d] (pre-scaled by log2e/8)
__device__ __nv_bfloat16 g_ql[BB*HH*TT*DD];
__device__ __nv_bfloat16 g_kh[BB*HH*TT*DD]; // [b,h,t,d]
__device__ __nv_bfloat16 g_kl[BB*HH*TT*DD];
__device__ __nv_bfloat16 g_vth[BB*HH*DD*TT]; // V^T [b,h,d,t]
__device__ __nv_bfloat16 g_vtl[BB*HH*DD*TT];

// ---------------- helpers ---------------------------------------------------
__device__ __forceinline__ uint32_t smem_u32(const void* p) {
    uint32_t a;
    asm("{ .reg .u64 t; cvta.to.shared.u64 t, %1; cvt.u32.u64 %0, t; }"
        : "=r"(a) : "l"(p));
    return a;
}

#define CP_ASYNC16(s, g) \
    asm volatile("cp.async.cg.shared.global [%0], [%1], 16;" :: "r"(s), "l"(g) : "memory")
#define CP_COMMIT()  asm volatile("cp.async.commit_group;" ::: "memory")
#define CP_WAIT(n)   asm volatile("cp.async.wait_group %0;" :: "n"(n) : "memory")

__device__ __forceinline__ void ldmx4(uint32_t* r, uint32_t addr) {
    asm volatile("ldmatrix.sync.aligned.m8n8.x4.shared.b16 {%0,%1,%2,%3}, [%4];"
        : "=r"(r[0]), "=r"(r[1]), "=r"(r[2]), "=r"(r[3]) : "r"(addr));
}
__device__ __forceinline__ void mma16816(float* c, const uint32_t* a, const uint32_t* b) {
    asm volatile(
        "mma.sync.aligned.m16n8k16.row.col.f32.bf16.bf16.f32 "
        "{%0,%1,%2,%3}, {%4,%5,%6,%7}, {%8,%9}, {%0,%1,%2,%3};"
        : "+f"(c[0]), "+f"(c[1]), "+f"(c[2]), "+f"(c[3])
        : "r"(a[0]), "r"(a[1]), "r"(a[2]), "r"(a[3]), "r"(b[0]), "r"(b[1]));
}
// raw MUFU exp2 (inputs finite, <= 0 in our use; approx err ~2^-22)
__device__ __forceinline__ float ex2(float x) {
    float y;
    asm("ex2.approx.ftz.f32 %0, %1;" : "=f"(y) : "f"(x));
    return y;
}
// pack (c0 -> low, c1 -> high) as bf16x2 (hi) plus residual pair (lo)
__device__ __forceinline__ void split2(float c0, float c1, uint32_t& h, uint32_t& l) {
    const __nv_bfloat16 b0 = __float2bfloat16(c0);
    const __nv_bfloat16 b1 = __float2bfloat16(c1);
    asm("cvt.rn.bf16x2.f32 %0, %1, %2;" : "=r"(h) : "f"(c1), "f"(c0));
    const float r0 = c0 - __bfloat162float(b0);
    const float r1 = c1 - __bfloat162float(b1);
    asm("cvt.rn.bf16x2.f32 %0, %1, %2;" : "=r"(l) : "f"(r1), "f"(r0));
}

// ---------------------------------------------------------------------------
// bf16 HMMA split GEMM, fused passes, single-sync pipeline, 2 CTAs/SM.
// MMA issue is pass-major over mt: each accumulator revisited at distance 4
// (was 2) to cover mma.sync latency.
// ---------------------------------------------------------------------------
#define SAB 80                       // smem row stride, bytes (40 halves)
#define T_BYTES (128*SAB)            // one 128x32 bf16 tile: 10240 B
#define STAGE_BYTES (4*T_BYTES)      // Ah, Al, Bh, Bl: 40960 B
#define NS 2
#define GEMM_SMEM (NS*STAGE_BYTES)   // 81920 B
#define NITER 32                     // 1024/32
#define SCQ 0.18033688011112042f     // (1/8) * log2(e)

template<int MODE>
__global__ __launch_bounds__(256, 2)
void gemm_tc(const __nv_bfloat16* __restrict__ Ah,
             const __nv_bfloat16* __restrict__ Al,
             float* __restrict__ outp,
             const float* __restrict__ bias0,
             const float* __restrict__ bias1,
             const float* __restrict__ bias2)
{
    extern __shared__ __align__(128) char dsm[];

    const int tid    = threadIdx.x;
    const int wid    = tid >> 5;
    const int lane   = tid & 31;
    const int warp_m = wid & 3;
    const int warp_n = wid >> 2;
    const int bn     = blockIdx.x * 128;
    const int bm     = blockIdx.y * 128;
    const int z      = (MODE == 0) ? blockIdx.z : 3;

    const __nv_bfloat16* Bhp = g_wth + (size_t)z * (CC * CC);
    const __nv_bfloat16* Blp = g_wtl + (size_t)z * (CC * CC);
    const float* bias = (MODE == 0) ? ((z == 0) ? bias0 : (z == 1) ? bias1 : bias2) : bias0;

    const uint32_t smem_base = smem_u32(dsm);

    float acc[2][8][4];
    #pragma unroll
    for (int mt = 0; mt < 2; mt++)
        #pragma unroll
        for (int nt = 0; nt < 8; nt++)
            #pragma unroll
            for (int e = 0; e < 4; e++) acc[mt][nt][e] = 0.0f;

    auto load_stage = [&](int L) {
        const int slot = L & (NS - 1);
        const int kt   = L * 32;
        const uint32_t s0 = smem_base + slot * STAGE_BYTES;
        #pragma unroll
        for (int i = 0; i < 2; i++) {
            const int idx = i * 256 + tid;          // 0..511
            const int r = idx >> 2, c = idx & 3;    // row, 16B chunk
            const uint32_t so = r * SAB + c * 16;
            const size_t ga = (size_t)(bm + r) * CC + kt + c * 8;
            const size_t gb = (size_t)(bn + r) * CC + kt + c * 8;
            CP_ASYNC16(s0 + so,               Ah  + ga);
            CP_ASYNC16(s0 + T_BYTES + so,     Al  + ga);
            CP_ASYNC16(s0 + 2*T_BYTES + so,   Bhp + gb);
            CP_ASYNC16(s0 + 3*T_BYTES + so,   Blp + gb);
        }
    };

    load_stage(0); CP_COMMIT();

    for (int it = 0; it < NITER; it++) {
        CP_WAIT(0);
        __syncthreads();
        if (it + 1 < NITER) load_stage(it + 1);
        CP_COMMIT();

        const uint32_t s0 = smem_base + (it & (NS - 1)) * STAGE_BYTES;
        const uint32_t aBase = s0 + (warp_m * 32 + (lane & 15)) * SAB + (lane >> 4) * 16;
        const uint32_t bBase = s0 + 2*T_BYTES
                                  + (warp_n * 64 + (lane & 7) + ((lane >> 4) << 3)) * SAB
                                  + ((lane >> 3) & 1) * 16;
        #pragma unroll
        for (int kk = 0; kk < 2; kk++) {       // k = 0, 16
            uint32_t ah[2][4], al[2][4];
            ldmx4(ah[0], aBase + kk * 32);
            ldmx4(ah[1], aBase + 16 * SAB + kk * 32);
            ldmx4(al[0], aBase + T_BYTES + kk * 32);
            ldmx4(al[1], aBase + T_BYTES + 16 * SAB + kk * 32);
            #pragma unroll
            for (int np = 0; np < 4; np++) {
                uint32_t bh[4], bl[4];
                ldmx4(bh, bBase + np * 16 * SAB + kk * 32);
                ldmx4(bl, bBase + T_BYTES + np * 16 * SAB + kk * 32);
                // pass-major: each acc quad revisited at distance 4
                mma16816(acc[0][np * 2 + 0], ah[0], &bh[0]);
                mma16816(acc[0][np * 2 + 1], ah[0], &bh[2]);
                mma16816(acc[1][np * 2 + 0], ah[1], &bh[0]);
                mma16816(acc[1][np * 2 + 1], ah[1], &bh[2]);
                mma16816(acc[0][np * 2 + 0], ah[0], &bl[0]);
                mma16816(acc[0][np * 2 + 1], ah[0], &bl[2]);
                mma16816(acc[1][np * 2 + 0], ah[1], &bl[0]);
                mma16816(acc[1][np * 2 + 1], ah[1], &bl[2]);
                mma16816(acc[0][np * 2 + 0], al[0], &bh[0]);
                mma16816(acc[0][np * 2 + 1], al[0], &bh[2]);
                mma16816(acc[1][np * 2 + 0], al[1], &bh[0]);
                mma16816(acc[1][np * 2 + 1], al[1], &bh[2]);
            }
        }
    }

    // epilogue
    const int groupID = lane >> 2;
    const int tig     = lane & 3;

    #pragma unroll
    for (int mt = 0; mt < 2; mt++) {
        #pragma unroll
        for (int nt = 0; nt < 8; nt++) {
            const int col = bn + warp_n * 64 + nt * 8 + tig * 2;
            const float b0 = bias[col], b1 = bias[col + 1];
            #pragma unroll
            for (int half = 0; half < 2; half++) {
                const int rg = bm + warp_m * 32 + mt * 16 + groupID + half * 8;
                float vx = acc[mt][nt][half * 2 + 0] + b0;
                float vy = acc[mt][nt][half * 2 + 1] + b1;
                if (MODE == 1) {
                    float2 v; v.x = vx; v.y = vy;
                    *(float2*)&outp[(size_t)rg * CC + col] = v;
                } else {
                    if (z == 0) { vx *= SCQ; vy *= SCQ; }   // pre-scale Q
                    const int b = rg >> 11, t = rg & 2047;
                    const int h = col >> 6, d = col & 63;
                    const __nv_bfloat16 hx = __float2bfloat16(vx);
                    const __nv_bfloat16 hy = __float2bfloat16(vy);
                    const __nv_bfloat16 lx = __float2bfloat16(vx - __bfloat162float(hx));
                    const __nv_bfloat16 ly = __float2bfloat16(vy - __bfloat162float(hy));
                    if (z == 2) {
                        // V^T [b,h,d,t]
                        const size_t a0 = ((size_t)(b * HH + h) * DD + d) * TT + t;
                        g_vth[a0]      = hx;  g_vtl[a0]      = lx;
                        g_vth[a0 + TT] = hy;  g_vtl[a0 + TT] = ly;
                    } else {
                        __nv_bfloat16* dh = (z == 0) ? g_qh : g_kh;
                        __nv_bfloat16* dl = (z == 0) ? g_ql : g_kl;
                        const size_t a0 = ((size_t)(b * HH + h) * TT + t) * DD + d;
                        ushort2 Hu, Lu;
                        Hu.x = __bfloat16_as_ushort(hx); Hu.y = __bfloat16_as_ushort(hy);
                        Lu.x = __bfloat16_as_ushort(lx); Lu.y = __bfloat16_as_ushort(ly);
                        *(ushort2*)&dh[a0] = Hu;
                        *(ushort2*)&dl[a0] = Lu;
                    }
                }
            }
        }
    }
}

// ---------------------------------------------------------------------------
// fp32 -> (hi, lo) bf16 split, vectorized by float4
// ---------------------------------------------------------------------------
__global__ __launch_bounds__(256)
void split_f32(const float4* __restrict__ in, __nv_bfloat16* __restrict__ hi,
               __nv_bfloat16* __restrict__ lo)
{
    const int i = blockIdx.x * 256 + threadIdx.x;
    const float4 v = in[i];
    __nv_bfloat16 h0 = __float2bfloat16(v.x);
    __nv_bfloat16 h1 = __float2bfloat16(v.y);
    __nv_bfloat16 h2 = __float2bfloat16(v.z);
    __nv_bfloat16 h3 = __float2bfloat16(v.w);
    ushort4 H, L;
    H.x = __bfloat16_as_ushort(h0); H.y = __bfloat16_as_ushort(h1);
    H.z = __bfloat16_as_ushort(h2); H.w = __bfloat16_as_ushort(h3);
    L.x = __bfloat16_as_ushort(__float2bfloat16(v.x - __bfloat162float(h0)));
    L.y = __bfloat16_as_ushort(__float2bfloat16(v.y - __bfloat162float(h1)));
    L.z = __bfloat16_as_ushort(__float2bfloat16(v.z - __bfloat162float(h2)));
    L.w = __bfloat16_as_ushort(__float2bfloat16(v.w - __bfloat162float(h3)));
    *(ushort4*)(hi + (size_t)i * 4) = H;
    *(ushort4*)(lo + (size_t)i * 4) = L;
}

// ---------------------------------------------------------------------------
// Transpose + split all 4 weight matrices: W[k][n] fp32 -> Wt hi/lo [n][k] bf16
// ---------------------------------------------------------------------------
__global__ __launch_bounds__(256)
void transpose_split_w(const float* __restrict__ Wq, const float* __restrict__ Wk,
                       const float* __restrict__ Wv, const float* __restrict__ Wo)
{
    __shared__ float tile[32][33];
    const int zz = blockIdx.z;
    const float* W = (zz == 0) ? Wq : (zz == 1) ? Wk : (zz == 2) ? Wv : Wo;
    const int tx = threadIdx.x, ty = threadIdx.y;
    const int n0 = blockIdx.x * 32;
    const int k0 = blockIdx.y * 32;
    #pragma unroll
    for (int i = ty; i < 32; i += 8)
        tile[i][tx] = W[(size_t)(k0 + i) * CC + n0 + tx];
    __syncthreads();
    __nv_bfloat16* oh = g_wth + (size_t)zz * (CC * CC);
    __nv_bfloat16* ol = g_wtl + (size_t)zz * (CC * CC);
    #pragma unroll
    for (int i = ty; i < 32; i += 8) {
        const float v = tile[tx][i];
        const __nv_bfloat16 h = __float2bfloat16(v);
        oh[(size_t)(n0 + i) * CC + k0 + tx] = h;
        ol[(size_t)(n0 + i) * CC + k0 + tx] = __float2bfloat16(v - __bfloat162float(h));
    }
}

// ---------------------------------------------------------------------------
// HMMA flash-attention, causal, fused passes, 2 CTAs/SM.
// S and PV MMA issue is np-paired pass-major: accumulators revisited at
// distance 4 to cover mma.sync latency.
// ---------------------------------------------------------------------------
#define SKB 144                       // smem row stride bytes (64 halves + pad)
#define KTB (64*SKB)                  // one 64x64 bf16 tile: 9216 B
#define QREG (4*KTB)                  // Qh + Ql: 36864 B
#define ATT_STAGE (4*KTB)             // Kh,Kl,Vth,Vtl: 36864 B
#define ATT_SMEM (QREG + 2*ATT_STAGE) // 110592 B

__global__ __launch_bounds__(256, 2)
void attn_mma()
{
    extern __shared__ __align__(128) char dsm[];
    const int tid  = threadIdx.x;
    const int wid  = tid >> 5;
    const int lane = tid & 31;
    const int g    = lane >> 2;
    const int tig  = lane & 3;
    const int qb   = (int)gridDim.x - 1 - (int)blockIdx.x;   // long blocks first
    const int bh   = blockIdx.y;
    const int bI   = bh >> 4;
    const int hd   = bh & 15;
    const uint32_t sbase = smem_u32(dsm);
    const uint32_t kvbase = sbase + QREG;

    // ---- stage Q (hi/lo) into persistent region [Qh | Ql] ----
    {
        const size_t qoff = ((size_t)bh * TT + (size_t)qb * 128) * DD;
        #pragma unroll
        for (int i = 0; i < 4; i++) {
            const int idx = i * 256 + tid;           // 0..1023
            const int r = idx >> 3, c = idx & 7;
            CP_ASYNC16(sbase + r * SKB + c * 16,         g_qh + qoff + (size_t)r * DD + c * 8);
            CP_ASYNC16(sbase + 2*KTB + r * SKB + c * 16, g_ql + qoff + (size_t)r * DD + c * 8);
        }
    }

    float c_o[8][4];
    #pragma unroll
    for (int nt = 0; nt < 8; nt++)
        #pragma unroll
        for (int e = 0; e < 4; e++) c_o[nt][e] = 0.0f;
    float mI[2] = {-1e30f, -1e30f}, lI[2] = {0.0f, 0.0f};

    auto load_kv = [&](int j) {
        const uint32_t sb = kvbase + (j & 1) * ATT_STAGE;
        #pragma unroll
        for (int i = 0; i < 2; i++) {
            const int idx = i * 256 + tid;           // 0..511
            const int r = idx >> 3, c = idx & 7;
            const size_t gk = ((size_t)bh * TT + j * 64 + r) * DD + c * 8;
            CP_ASYNC16(sb + r * SKB + c * 16,       g_kh + gk);
            CP_ASYNC16(sb + KTB + r * SKB + c * 16, g_kl + gk);
            const size_t gv = ((size_t)bh * DD + r) * TT + j * 64 + c * 8;
            CP_ASYNC16(sb + 2*KTB + r * SKB + c * 16, g_vth + gv);
            CP_ASYNC16(sb + 3*KTB + r * SKB + c * 16, g_vtl + gv);
        }
    };

    CP_COMMIT();                 // group: Q
    const int ntiles = 2 * qb + 2;
    load_kv(0); CP_COMMIT();     // group: kv0

    const uint32_t qB = sbase + (wid * 16 + (lane & 15)) * SKB + (lane >> 4) * 16;

    for (int j = 0; j < ntiles; j++) {
        CP_WAIT(0);                // tile j (and Q) arrived
        __syncthreads();           // all warps done with tile j-1 (slot gets overwritten)
        if (j + 1 < ntiles) load_kv(j + 1);
        CP_COMMIT();

        const uint32_t sb = kvbase + (j & 1) * ATT_STAGE;
        const uint32_t bB = sb + ((lane & 7) + ((lane >> 4) << 3)) * SKB
                               + ((lane >> 3) & 1) * 16;

        // ---- S = Q K^T (fused 3 passes; np-paired, pass-major) ----
        float c_s[8][4];
        #pragma unroll
        for (int nt = 0; nt < 8; nt++)
            #pragma unroll
            for (int e = 0; e < 4; e++) c_s[nt][e] = 0.0f;

        #pragma unroll
        for (int kk = 0; kk < 4; kk++) {
            uint32_t qh_[4], ql_[4];
            ldmx4(qh_, qB + kk * 32);
            ldmx4(ql_, qB + 2*KTB + kk * 32);
            #pragma unroll
            for (int np2 = 0; np2 < 4; np2 += 2) {
                uint32_t bh0[4], bh1[4], bl0[4], bl1[4];
                ldmx4(bh0, bB + np2 * 16 * SKB + kk * 32);
                ldmx4(bh1, bB + (np2 + 1) * 16 * SKB + kk * 32);
                ldmx4(bl0, bB + KTB + np2 * 16 * SKB + kk * 32);
                ldmx4(bl1, bB + KTB + (np2 + 1) * 16 * SKB + kk * 32);
                float* a0 = c_s[np2 * 2 + 0];
                float* a1 = c_s[np2 * 2 + 1];
                float* a2 = c_s[np2 * 2 + 2];
                float* a3 = c_s[np2 * 2 + 3];
                mma16816(a0, qh_, &bh0[0]);
                mma16816(a1, qh_, &bh0[2]);
                mma16816(a2, qh_, &bh1[0]);
                mma16816(a3, qh_, &bh1[2]);
                mma16816(a0, qh_, &bl0[0]);
                mma16816(a1, qh_, &bl0[2]);
                mma16816(a2, qh_, &bl1[0]);
                mma16816(a3, qh_, &bl1[2]);
                mma16816(a0, ql_, &bh0[0]);
                mma16816(a1, ql_, &bh0[2]);
                mma16816(a2, ql_, &bh1[0]);
                mma16816(a3, ql_, &bh1[2]);
            }
        }

        // ---- causal mask (only on the 2 diagonal tiles; uniform branch) ----
        if (j >= 2 * qb) {
            const int jbase = j * 64;
            #pragma unroll
            for (int hh = 0; hh < 2; hh++) {
                const int qrow = qb * 128 + wid * 16 + g + hh * 8;
                #pragma unroll
                for (int nt = 0; nt < 8; nt++)
                    #pragma unroll
                    for (int e = 0; e < 2; e++) {
                        const int col = jbase + nt * 8 + tig * 2 + e;
                        if (col > qrow) c_s[nt][hh * 2 + e] = -1e30f;
                    }
            }
        }

        // ---- online softmax (values already in exp2 domain) ----
        #pragma unroll
        for (int hh = 0; hh < 2; hh++) {
            float mx = -1e30f;
            #pragma unroll
            for (int nt = 0; nt < 8; nt++) {
                mx = fmaxf(mx, c_s[nt][hh * 2 + 0]);
                mx = fmaxf(mx, c_s[nt][hh * 2 + 1]);
            }
            mx = fmaxf(mx, __shfl_xor_sync(0xffffffffu, mx, 1));
            mx = fmaxf(mx, __shfl_xor_sync(0xffffffffu, mx, 2));
            const float mN = fmaxf(mI[hh], mx);
            const float corr = ex2(mI[hh] - mN);
            mI[hh] = mN;
            float rs = 0.0f;
            #pragma unroll
            for (int nt = 0; nt < 8; nt++)
                #pragma unroll
                for (int e = 0; e < 2; e++) {
                    const float p = ex2(c_s[nt][hh * 2 + e] - mN);
                    c_s[nt][hh * 2 + e] = p;
                    rs += p;
                }
            rs += __shfl_xor_sync(0xffffffffu, rs, 1);
            rs += __shfl_xor_sync(0xffffffffu, rs, 2);
            lI[hh] = lI[hh] * corr + rs;
            #pragma unroll
            for (int nt = 0; nt < 8; nt++) {
                c_o[nt][hh * 2 + 0] *= corr;
                c_o[nt][hh * 2 + 1] *= corr;
            }
        }

        // ---- re-pack P as A fragments (hi/lo) ----
        uint32_t phf[4][4], plf[4][4];
        #pragma unroll
        for (int kk = 0; kk < 4; kk++) {
            split2(c_s[2*kk][0],   c_s[2*kk][1],   phf[kk][0], plf[kk][0]);
            split2(c_s[2*kk][2],   c_s[2*kk][3],   phf[kk][1], plf[kk][1]);
            split2(c_s[2*kk+1][0], c_s[2*kk+1][1], phf[kk][2], plf[kk][2]);
            split2(c_s[2*kk+1][2], c_s[2*kk+1][3], phf[kk][3], plf[kk][3]);
        }

        // ---- O += P V (fused 3 passes; np-paired, pass-major) ----
        const uint32_t vB = bB + 2 * KTB;
        #pragma unroll
        for (int kk = 0; kk < 4; kk++) {
            #pragma unroll
            for (int np2 = 0; np2 < 4; np2 += 2) {
                uint32_t vh0[4], vh1[4], vl0[4], vl1[4];
                ldmx4(vh0, vB + np2 * 16 * SKB + kk * 32);
                ldmx4(vh1, vB + (np2 + 1) * 16 * SKB + kk * 32);
                ldmx4(vl0, vB + KTB + np2 * 16 * SKB + kk * 32);
                ldmx4(vl1, vB + KTB + (np2 + 1) * 16 * SKB + kk * 32);
                float* a0 = c_o[np2 * 2 + 0];
                float* a1 = c_o[np2 * 2 + 1];
                float* a2 = c_o[np2 * 2 + 2];
                float* a3 = c_o[np2 * 2 + 3];
                mma16816(a0, phf[kk], &vh0[0]);
                mma16816(a1, phf[kk], &vh0[2]);
                mma16816(a2, phf[kk], &vh1[0]);
                mma16816(a3, phf[kk], &vh1[2]);
                mma16816(a0, phf[kk], &vl0[0]);
                mma16816(a1, phf[kk], &vl0[2]);
                mma16816(a2, phf[kk], &vl1[0]);
                mma16816(a3, phf[kk], &vl1[2]);
                mma16816(a0, plf[kk], &vh0[0]);
                mma16816(a1, plf[kk], &vh0[2]);
                mma16816(a2, plf[kk], &vh1[0]);
                mma16816(a3, plf[kk], &vh1[2]);
            }
        }
    }

    // ---- epilogue: O/l -> bf16 hi/lo into g_ah/g_al [b,t,c] ----
    #pragma unroll
    for (int hh = 0; hh < 2; hh++) {
        const float inv = 1.0f / lI[hh];
        const int t = qb * 128 + wid * 16 + g + hh * 8;
        const size_t rowb = ((size_t)bI * TT + t) * CC + hd * 64;
        #pragma unroll
        for (int nt = 0; nt < 8; nt++) {
            const float v0 = c_o[nt][hh * 2 + 0] * inv;
            const float v1 = c_o[nt][hh * 2 + 1] * inv;
            const __nv_bfloat16 h0 = __float2bfloat16(v0);
            const __nv_bfloat16 h1 = __float2bfloat16(v1);
            ushort2 Hu, Lu;
            Hu.x = __bfloat16_as_ushort(h0);
            Hu.y = __bfloat16_as_ushort(h1);
            Lu.x = __bfloat16_as_ushort(__float2bfloat16(v0 - __bfloat162float(h0)));
            Lu.y = __bfloat16_as_ushort(__float2bfloat16(v1 - __bfloat162float(h1)));
            const size_t a0 = rowb + nt * 8 + tig * 2;
            *(ushort2*)&g_ah[a0] = Hu;
            *(ushort2*)&g_al[a0] = Lu;
        }
    }
}

// ---------------------------------------------------------------------------
extern "C" void kernel_launch(void* const* d_in, const int* in_sizes, int n_in,
                              void* d_out, int out_size)
{
    const float* x  = (const float*)d_in[0];
    const float* Wq = (const float*)d_in[1];
    const float* bq = (const float*)d_in[2];
    const float* Wk = (const float*)d_in[3];
    const float* bk = (const float*)d_in[4];
    const float* Wv = (const float*)d_in[5];
    const float* bv = (const float*)d_in[6];
    const float* Wo = (const float*)d_in[7];
    const float* bo = (const float*)d_in[8];
    float* out = (float*)d_out;

    cudaFuncSetAttribute(gemm_tc<0>, cudaFuncAttributeMaxDynamicSharedMemorySize, GEMM_SMEM);
    cudaFuncSetAttribute(gemm_tc<1>, cudaFuncAttributeMaxDynamicSharedMemorySize, GEMM_SMEM);
    cudaFuncSetAttribute(attn_mma,   cudaFuncAttributeMaxDynamicSharedMemorySize, ATT_SMEM);

    __nv_bfloat16 *xh, *xl, *ah, *al;
    cudaGetSymbolAddress((void**)&xh, g_xh);
    cudaGetSymbolAddress((void**)&xl, g_xl);
    cudaGetSymbolAddress((void**)&ah, g_ah);
    cudaGetSymbolAddress((void**)&al, g_al);

    // split x into bf16 hi/lo, transpose+split all weights
    split_f32<<<MMr * CC / 1024, 256>>>((const float4*)x, xh, xl);
    transpose_split_w<<<dim3(32, 32, 4), dim3(32, 8)>>>(Wq, Wk, Wv, Wo);

    // QKV projections (HMMA) -> bf16 hi/lo Q/K/V^T (Q pre-scaled)
    gemm_tc<0><<<dim3(8, 32, 3), 256, GEMM_SMEM>>>(xh, xl, nullptr, bq, bk, bv);

    // attention (HMMA) -> bf16 hi/lo attn output
    attn_mma<<<dim3(16, 32), 256, ATT_SMEM>>>();

    // output projection (HMMA)
    gemm_tc<1><<<dim3(8, 32, 1), 256, GEMM_SMEM>>>(ah, al, out, bo, bo, bo);
}

// round 15
// speedup vs baseline: 1.0053x; 1.0015x over previous
#include <cuda_runtime.h>
#include <cuda_bf16.h>
#include <cstdint>

// Problem constants
#define BB 2
#define TT 2048
#define CC 1024
#define HH 16
#define DD 64
#define MMr (BB*TT)          // 4096

// ---------------- scratch (device globals; no allocation allowed) ----------
__device__ __nv_bfloat16 g_xh[MMr*CC];
__device__ __nv_bfloat16 g_xl[MMr*CC];
__device__ __nv_bfloat16 g_ah[MMr*CC];      // attn output hi [b,t,c]
__device__ __nv_bfloat16 g_al[MMr*CC];      // attn output lo
__device__ __nv_bfloat16 g_wth[4*CC*CC];    // W^T hi, [n][k], 4 matrices
__device__ __nv_bfloat16 g_wtl[4*CC*CC];    // W^T lo
__device__ __nv_bfloat16 g_qh[BB*HH*TT*DD]; // [b,h,t,d] (pre-scaled by log2e/8)
__device__ __nv_bfloat16 g_ql[BB*HH*TT*DD];
__device__ __nv_bfloat16 g_kh[BB*HH*TT*DD]; // [b,h,t,d]
__device__ __nv_bfloat16 g_kl[BB*HH*TT*DD];
__device__ __nv_bfloat16 g_vth[BB*HH*DD*TT]; // V^T [b,h,d,t]
__device__ __nv_bfloat16 g_vtl[BB*HH*DD*TT];

// ---------------- helpers ---------------------------------------------------
__device__ __forceinline__ uint32_t smem_u32(const void* p) {
    uint32_t a;
    asm("{ .reg .u64 t; cvta.to.shared.u64 t, %1; cvt.u32.u64 %0, t; }"
        : "=r"(a) : "l"(p));
    return a;
}

#define CP_ASYNC16(s, g) \
    asm volatile("cp.async.cg.shared.global [%0], [%1], 16;" :: "r"(s), "l"(g) : "memory")
#define CP_COMMIT()  asm volatile("cp.async.commit_group;" ::: "memory")
#define CP_WAIT(n)   asm volatile("cp.async.wait_group %0;" :: "n"(n) : "memory")

__device__ __forceinline__ void ldmx4(uint32_t* r, uint32_t addr) {
    asm volatile("ldmatrix.sync.aligned.m8n8.x4.shared.b16 {%0,%1,%2,%3}, [%4];"
        : "=r"(r[0]), "=r"(r[1]), "=r"(r[2]), "=r"(r[3]) : "r"(addr));
}
__device__ __forceinline__ void mma16816(float* c, const uint32_t* a, const uint32_t* b) {
    asm volatile(
        "mma.sync.aligned.m16n8k16.row.col.f32.bf16.bf16.f32 "
        "{%0,%1,%2,%3}, {%4,%5,%6,%7}, {%8,%9}, {%0,%1,%2,%3};"
        : "+f"(c[0]), "+f"(c[1]), "+f"(c[2]), "+f"(c[3])
        : "r"(a[0]), "r"(a[1]), "r"(a[2]), "r"(a[3]), "r"(b[0]), "r"(b[1]));
}
// mma with A fragment given as bit-aliased floats (in-place packed P)
__device__ __forceinline__ void mma16816f(float* c, const float* af, const uint32_t* b) {
    asm volatile(
        "mma.sync.aligned.m16n8k16.row.col.f32.bf16.bf16.f32 "
        "{%0,%1,%2,%3}, {%4,%5,%6,%7}, {%8,%9}, {%0,%1,%2,%3};"
        : "+f"(c[0]), "+f"(c[1]), "+f"(c[2]), "+f"(c[3])
        : "r"(__float_as_uint(af[0])), "r"(__float_as_uint(af[1])),
          "r"(__float_as_uint(af[2])), "r"(__float_as_uint(af[3])),
          "r"(b[0]), "r"(b[1]));
}
// raw MUFU exp2 (inputs finite, <= 0 in our use; approx err ~2^-22)
__device__ __forceinline__ float ex2(float x) {
    float y;
    asm("ex2.approx.ftz.f32 %0, %1;" : "=f"(y) : "f"(x));
    return y;
}
// pack (c0 -> low, c1 -> high) as bf16x2 (hi) plus residual pair (lo)
__device__ __forceinline__ void split2(float c0, float c1, uint32_t& h, uint32_t& l) {
    const __nv_bfloat16 b0 = __float2bfloat16(c0);
    const __nv_bfloat16 b1 = __float2bfloat16(c1);
    asm("cvt.rn.bf16x2.f32 %0, %1, %2;" : "=r"(h) : "f"(c1), "f"(c0));
    const float r0 = c0 - __bfloat162float(b0);
    const float r1 = c1 - __bfloat162float(b1);
    asm("cvt.rn.bf16x2.f32 %0, %1, %2;" : "=r"(l) : "f"(r1), "f"(r0));
}

// ---------------------------------------------------------------------------
// bf16 HMMA split GEMM, fused passes, single-sync pipeline, 2 CTAs/SM.
// (unchanged from round 14)
// ---------------------------------------------------------------------------
#define SAB 80                       // smem row stride, bytes (40 halves)
#define T_BYTES (128*SAB)            // one 128x32 bf16 tile: 10240 B
#define STAGE_BYTES (4*T_BYTES)      // Ah, Al, Bh, Bl: 40960 B
#define NS 2
#define GEMM_SMEM (NS*STAGE_BYTES)   // 81920 B
#define NITER 32                     // 1024/32
#define SCQ 0.18033688011112042f     // (1/8) * log2(e)

template<int MODE>
__global__ __launch_bounds__(256, 2)
void gemm_tc(const __nv_bfloat16* __restrict__ Ah,
             const __nv_bfloat16* __restrict__ Al,
             float* __restrict__ outp,
             const float* __restrict__ bias0,
             const float* __restrict__ bias1,
             const float* __restrict__ bias2)
{
    extern __shared__ __align__(128) char dsm[];

    const int tid    = threadIdx.x;
    const int wid    = tid >> 5;
    const int lane   = tid & 31;
    const int warp_m = wid & 3;
    const int warp_n = wid >> 2;
    const int bn     = blockIdx.x * 128;
    const int bm     = blockIdx.y * 128;
    const int z      = (MODE == 0) ? blockIdx.z : 3;

    const __nv_bfloat16* Bhp = g_wth + (size_t)z * (CC * CC);
    const __nv_bfloat16* Blp = g_wtl + (size_t)z * (CC * CC);
    const float* bias = (MODE == 0) ? ((z == 0) ? bias0 : (z == 1) ? bias1 : bias2) : bias0;

    const uint32_t smem_base = smem_u32(dsm);

    float acc[2][8][4];
    #pragma unroll
    for (int mt = 0; mt < 2; mt++)
        #pragma unroll
        for (int nt = 0; nt < 8; nt++)
            #pragma unroll
            for (int e = 0; e < 4; e++) acc[mt][nt][e] = 0.0f;

    auto load_stage = [&](int L) {
        const int slot = L & (NS - 1);
        const int kt   = L * 32;
        const uint32_t s0 = smem_base + slot * STAGE_BYTES;
        #pragma unroll
        for (int i = 0; i < 2; i++) {
            const int idx = i * 256 + tid;          // 0..511
            const int r = idx >> 2, c = idx & 3;    // row, 16B chunk
            const uint32_t so = r * SAB + c * 16;
            const size_t ga = (size_t)(bm + r) * CC + kt + c * 8;
            const size_t gb = (size_t)(bn + r) * CC + kt + c * 8;
            CP_ASYNC16(s0 + so,               Ah  + ga);
            CP_ASYNC16(s0 + T_BYTES + so,     Al  + ga);
            CP_ASYNC16(s0 + 2*T_BYTES + so,   Bhp + gb);
            CP_ASYNC16(s0 + 3*T_BYTES + so,   Blp + gb);
        }
    };

    load_stage(0); CP_COMMIT();

    for (int it = 0; it < NITER; it++) {
        CP_WAIT(0);
        __syncthreads();
        if (it + 1 < NITER) load_stage(it + 1);
        CP_COMMIT();

        const uint32_t s0 = smem_base + (it & (NS - 1)) * STAGE_BYTES;
        const uint32_t aBase = s0 + (warp_m * 32 + (lane & 15)) * SAB + (lane >> 4) * 16;
        const uint32_t bBase = s0 + 2*T_BYTES
                                  + (warp_n * 64 + (lane & 7) + ((lane >> 4) << 3)) * SAB
                                  + ((lane >> 3) & 1) * 16;
        #pragma unroll
        for (int kk = 0; kk < 2; kk++) {       // k = 0, 16
            uint32_t ah[2][4], al[2][4];
            ldmx4(ah[0], aBase + kk * 32);
            ldmx4(ah[1], aBase + 16 * SAB + kk * 32);
            ldmx4(al[0], aBase + T_BYTES + kk * 32);
            ldmx4(al[1], aBase + T_BYTES + 16 * SAB + kk * 32);
            #pragma unroll
            for (int np = 0; np < 4; np++) {
                uint32_t bh[4], bl[4];
                ldmx4(bh, bBase + np * 16 * SAB + kk * 32);
                ldmx4(bl, bBase + T_BYTES + np * 16 * SAB + kk * 32);
                // pass-major: each acc quad revisited at distance 4
                mma16816(acc[0][np * 2 + 0], ah[0], &bh[0]);
                mma16816(acc[0][np * 2 + 1], ah[0], &bh[2]);
                mma16816(acc[1][np * 2 + 0], ah[1], &bh[0]);
                mma16816(acc[1][np * 2 + 1], ah[1], &bh[2]);
                mma16816(acc[0][np * 2 + 0], ah[0], &bl[0]);
                mma16816(acc[0][np * 2 + 1], ah[0], &bl[2]);
                mma16816(acc[1][np * 2 + 0], ah[1], &bl[0]);
                mma16816(acc[1][np * 2 + 1], ah[1], &bl[2]);
                mma16816(acc[0][np * 2 + 0], al[0], &bh[0]);
                mma16816(acc[0][np * 2 + 1], al[0], &bh[2]);
                mma16816(acc[1][np * 2 + 0], al[1], &bh[0]);
                mma16816(acc[1][np * 2 + 1], al[1], &bh[2]);
            }
        }
    }

    // epilogue
    const int groupID = lane >> 2;
    const int tig     = lane & 3;

    #pragma unroll
    for (int mt = 0; mt < 2; mt++) {
        #pragma unroll
        for (int nt = 0; nt < 8; nt++) {
            const int col = bn + warp_n * 64 + nt * 8 + tig * 2;
            const float b0 = bias[col], b1 = bias[col + 1];
            #pragma unroll
            for (int half = 0; half < 2; half++) {
                const int rg = bm + warp_m * 32 + mt * 16 + groupID + half * 8;
                float vx = acc[mt][nt][half * 2 + 0] + b0;
                float vy = acc[mt][nt][half * 2 + 1] + b1;
                if (MODE == 1) {
                    float2 v; v.x = vx; v.y = vy;
                    *(float2*)&outp[(size_t)rg * CC + col] = v;
                } else {
                    if (z == 0) { vx *= SCQ; vy *= SCQ; }   // pre-scale Q
                    const int b = rg >> 11, t = rg & 2047;
                    const int h = col >> 6, d = col & 63;
                    const __nv_bfloat16 hx = __float2bfloat16(vx);
                    const __nv_bfloat16 hy = __float2bfloat16(vy);
                    const __nv_bfloat16 lx = __float2bfloat16(vx - __bfloat162float(hx));
                    const __nv_bfloat16 ly = __float2bfloat16(vy - __bfloat162float(hy));
                    if (z == 2) {
                        // V^T [b,h,d,t]
                        const size_t a0 = ((size_t)(b * HH + h) * DD + d) * TT + t;
                        g_vth[a0]      = hx;  g_vtl[a0]      = lx;
                        g_vth[a0 + TT] = hy;  g_vtl[a0 + TT] = ly;
                    } else {
                        __nv_bfloat16* dh = (z == 0) ? g_qh : g_kh;
                        __nv_bfloat16* dl = (z == 0) ? g_ql : g_kl;
                        const size_t a0 = ((size_t)(b * HH + h) * TT + t) * DD + d;
                        ushort2 Hu, Lu;
                        Hu.x = __bfloat16_as_ushort(hx); Hu.y = __bfloat16_as_ushort(hy);
                        Lu.x = __bfloat16_as_ushort(lx); Lu.y = __bfloat16_as_ushort(ly);
                        *(ushort2*)&dh[a0] = Hu;
                        *(ushort2*)&dl[a0] = Lu;
                    }
                }
            }
        }
    }
}

// ---------------------------------------------------------------------------
// fp32 -> (hi, lo) bf16 split, vectorized by float4
// ---------------------------------------------------------------------------
__global__ __launch_bounds__(256)
void split_f32(const float4* __restrict__ in, __nv_bfloat16* __restrict__ hi,
               __nv_bfloat16* __restrict__ lo)
{
    const int i = blockIdx.x * 256 + threadIdx.x;
    const float4 v = in[i];
    __nv_bfloat16 h0 = __float2bfloat16(v.x);
    __nv_bfloat16 h1 = __float2bfloat16(v.y);
    __nv_bfloat16 h2 = __float2bfloat16(v.z);
    __nv_bfloat16 h3 = __float2bfloat16(v.w);
    ushort4 H, L;
    H.x = __bfloat16_as_ushort(h0); H.y = __bfloat16_as_ushort(h1);
    H.z = __bfloat16_as_ushort(h2); H.w = __bfloat16_as_ushort(h3);
    L.x = __bfloat16_as_ushort(__float2bfloat16(v.x - __bfloat162float(h0)));
    L.y = __bfloat16_as_ushort(__float2bfloat16(v.y - __bfloat162float(h1)));
    L.z = __bfloat16_as_ushort(__float2bfloat16(v.z - __bfloat162float(h2)));
    L.w = __bfloat16_as_ushort(__float2bfloat16(v.w - __bfloat162float(h3)));
    *(ushort4*)(hi + (size_t)i * 4) = H;
    *(ushort4*)(lo + (size_t)i * 4) = L;
}

// ---------------------------------------------------------------------------
// Transpose + split all 4 weight matrices: W[k][n] fp32 -> Wt hi/lo [n][k] bf16
// ---------------------------------------------------------------------------
__global__ __launch_bounds__(256)
void transpose_split_w(const float* __restrict__ Wq, const float* __restrict__ Wk,
                       const float* __restrict__ Wv, const float* __restrict__ Wo)
{
    __shared__ float tile[32][33];
    const int zz = blockIdx.z;
    const float* W = (zz == 0) ? Wq : (zz == 1) ? Wk : (zz == 2) ? Wv : Wo;
    const int tx = threadIdx.x, ty = threadIdx.y;
    const int n0 = blockIdx.x * 32;
    const int k0 = blockIdx.y * 32;
    #pragma unroll
    for (int i = ty; i < 32; i += 8)
        tile[i][tx] = W[(size_t)(k0 + i) * CC + n0 + tx];
    __syncthreads();
    __nv_bfloat16* oh = g_wth + (size_t)zz * (CC * CC);
    __nv_bfloat16* ol = g_wtl + (size_t)zz * (CC * CC);
    #pragma unroll
    for (int i = ty; i < 32; i += 8) {
        const float v = tile[tx][i];
        const __nv_bfloat16 h = __float2bfloat16(v);
        oh[(size_t)(n0 + i) * CC + k0 + tx] = h;
        ol[(size_t)(n0 + i) * CC + k0 + tx] = __float2bfloat16(v - __bfloat162float(h));
    }
}

// ---------------------------------------------------------------------------
// HMMA flash-attention, causal, fused passes, 2 CTAs/SM.
// P is packed IN PLACE into the S accumulator registers (no separate phf/plf)
// -> live-range demand ~96 regs, giving ptxas headroom to pipeline LDSM under
// the occupancy-2 128-reg cap.
// ---------------------------------------------------------------------------
#define SKB 144                       // smem row stride bytes (64 halves + pad)
#define KTB (64*SKB)                  // one 64x64 bf16 tile: 9216 B
#define QREG (4*KTB)                  // Qh + Ql: 36864 B
#define ATT_STAGE (4*KTB)             // Kh,Kl,Vth,Vtl: 36864 B
#define ATT_SMEM (QREG + 2*ATT_STAGE) // 110592 B

__global__ __launch_bounds__(256, 2)
void attn_mma()
{
    extern __shared__ __align__(128) char dsm[];
    const int tid  = threadIdx.x;
    const int wid  = tid >> 5;
    const int lane = tid & 31;
    const int g    = lane >> 2;
    const int tig  = lane & 3;
    const int qb   = (int)gridDim.x - 1 - (int)blockIdx.x;   // long blocks first
    const int bh   = blockIdx.y;
    const int bI   = bh >> 4;
    const int hd   = bh & 15;
    const uint32_t sbase = smem_u32(dsm);
    const uint32_t kvbase = sbase + QREG;

    // ---- stage Q (hi/lo) into persistent region [Qh | Ql] ----
    {
        const size_t qoff = ((size_t)bh * TT + (size_t)qb * 128) * DD;
        #pragma unroll
        for (int i = 0; i < 4; i++) {
            const int idx = i * 256 + tid;           // 0..1023
            const int r = idx >> 3, c = idx & 7;
            CP_ASYNC16(sbase + r * SKB + c * 16,         g_qh + qoff + (size_t)r * DD + c * 8);
            CP_ASYNC16(sbase + 2*KTB + r * SKB + c * 16, g_ql + qoff + (size_t)r * DD + c * 8);
        }
    }

    float c_o[8][4];
    #pragma unroll
    for (int nt = 0; nt < 8; nt++)
        #pragma unroll
        for (int e = 0; e < 4; e++) c_o[nt][e] = 0.0f;
    float mI[2] = {-1e30f, -1e30f}, lI[2] = {0.0f, 0.0f};

    auto load_kv = [&](int j) {
        const uint32_t sb = kvbase + (j & 1) * ATT_STAGE;
        #pragma unroll
        for (int i = 0; i < 2; i++) {
            const int idx = i * 256 + tid;           // 0..511
            const int r = idx >> 3, c = idx & 7;
            const size_t gk = ((size_t)bh * TT + j * 64 + r) * DD + c * 8;
            CP_ASYNC16(sb + r * SKB + c * 16,       g_kh + gk);
            CP_ASYNC16(sb + KTB + r * SKB + c * 16, g_kl + gk);
            const size_t gv = ((size_t)bh * DD + r) * TT + j * 64 + c * 8;
            CP_ASYNC16(sb + 2*KTB + r * SKB + c * 16, g_vth + gv);
            CP_ASYNC16(sb + 3*KTB + r * SKB + c * 16, g_vtl + gv);
        }
    };

    CP_COMMIT();                 // group: Q
    const int ntiles = 2 * qb + 2;
    load_kv(0); CP_COMMIT();     // group: kv0

    const uint32_t qB = sbase + (wid * 16 + (lane & 15)) * SKB + (lane >> 4) * 16;

    for (int j = 0; j < ntiles; j++) {
        CP_WAIT(0);                // tile j (and Q) arrived
        __syncthreads();           // all warps done with tile j-1 (slot gets overwritten)
        if (j + 1 < ntiles) load_kv(j + 1);
        CP_COMMIT();

        const uint32_t sb = kvbase + (j & 1) * ATT_STAGE;
        const uint32_t bB = sb + ((lane & 7) + ((lane >> 4) << 3)) * SKB
                               + ((lane >> 3) & 1) * 16;

        // ---- S = Q K^T (fused 3 passes; np-paired, pass-major) ----
        float c_s[8][4];
        #pragma unroll
        for (int nt = 0; nt < 8; nt++)
            #pragma unroll
            for (int e = 0; e < 4; e++) c_s[nt][e] = 0.0f;

        #pragma unroll
        for (int kk = 0; kk < 4; kk++) {
            uint32_t qh_[4], ql_[4];
            ldmx4(qh_, qB + kk * 32);
            ldmx4(ql_, qB + 2*KTB + kk * 32);
            #pragma unroll
            for (int np2 = 0; np2 < 4; np2 += 2) {
                uint32_t bh0[4], bh1[4], bl0[4], bl1[4];
                ldmx4(bh0, bB + np2 * 16 * SKB + kk * 32);
                ldmx4(bh1, bB + (np2 + 1) * 16 * SKB + kk * 32);
                ldmx4(bl0, bB + KTB + np2 * 16 * SKB + kk * 32);
                ldmx4(bl1, bB + KTB + (np2 + 1) * 16 * SKB + kk * 32);
                float* a0 = c_s[np2 * 2 + 0];
                float* a1 = c_s[np2 * 2 + 1];
                float* a2 = c_s[np2 * 2 + 2];
                float* a3 = c_s[np2 * 2 + 3];
                mma16816(a0, qh_, &bh0[0]);
                mma16816(a1, qh_, &bh0[2]);
                mma16816(a2, qh_, &bh1[0]);
                mma16816(a3, qh_, &bh1[2]);
                mma16816(a0, qh_, &bl0[0]);
                mma16816(a1, qh_, &bl0[2]);
                mma16816(a2, qh_, &bl1[0]);
                mma16816(a3, qh_, &bl1[2]);
                mma16816(a0, ql_, &bh0[0]);
                mma16816(a1, ql_, &bh0[2]);
                mma16816(a2, ql_, &bh1[0]);
                mma16816(a3, ql_, &bh1[2]);
            }
        }

        // ---- causal mask (only on the 2 diagonal tiles; uniform branch) ----
        if (j >= 2 * qb) {
            const int jbase = j * 64;
            #pragma unroll
            for (int hh = 0; hh < 2; hh++) {
                const int qrow = qb * 128 + wid * 16 + g + hh * 8;
                #pragma unroll
                for (int nt = 0; nt < 8; nt++)
                    #pragma unroll
                    for (int e = 0; e < 2; e++) {
                        const int col = jbase + nt * 8 + tig * 2 + e;
                        if (col > qrow) c_s[nt][hh * 2 + e] = -1e30f;
                    }
            }
        }

        // ---- online softmax (values already in exp2 domain) ----
        #pragma unroll
        for (int hh = 0; hh < 2; hh++) {
            float mx = -1e30f;
            #pragma unroll
            for (int nt = 0; nt < 8; nt++) {
                mx = fmaxf(mx, c_s[nt][hh * 2 + 0]);
                mx = fmaxf(mx, c_s[nt][hh * 2 + 1]);
            }
            mx = fmaxf(mx, __shfl_xor_sync(0xffffffffu, mx, 1));
            mx = fmaxf(mx, __shfl_xor_sync(0xffffffffu, mx, 2));
            const float mN = fmaxf(mI[hh], mx);
            const float corr = ex2(mI[hh] - mN);
            mI[hh] = mN;
            float rs = 0.0f;
            #pragma unroll
            for (int nt = 0; nt < 8; nt++)
                #pragma unroll
                for (int e = 0; e < 2; e++) {
                    const float p = ex2(c_s[nt][hh * 2 + e] - mN);
                    c_s[nt][hh * 2 + e] = p;
                    rs += p;
                }
            rs += __shfl_xor_sync(0xffffffffu, rs, 1);
            rs += __shfl_xor_sync(0xffffffffu, rs, 2);
            lI[hh] = lI[hh] * corr + rs;
            #pragma unroll
            for (int nt = 0; nt < 8; nt++) {
                c_o[nt][hh * 2 + 0] *= corr;
                c_o[nt][hh * 2 + 1] *= corr;
            }
        }

        // ---- pack P hi/lo IN PLACE into c_s (A-fragment layout, bit-aliased)
        // after: c_s[2k]   = {Ph0, Ph1, Pl0, Pl1}
        //        c_s[2k+1] = {Ph2, Ph3, Pl2, Pl3}   (k-th 16-wide A fragment)
        #pragma unroll
        for (int kk = 0; kk < 4; kk++) {
            uint32_t h0, l0, h1, l1, h2, l2, h3, l3;
            split2(c_s[2*kk][0],   c_s[2*kk][1],   h0, l0);
            split2(c_s[2*kk][2],   c_s[2*kk][3],   h1, l1);
            split2(c_s[2*kk+1][0], c_s[2*kk+1][1], h2, l2);
            split2(c_s[2*kk+1][2], c_s[2*kk+1][3], h3, l3);
            c_s[2*kk][0]   = __uint_as_float(h0);
            c_s[2*kk][1]   = __uint_as_float(h1);
            c_s[2*kk][2]   = __uint_as_float(l0);
            c_s[2*kk][3]   = __uint_as_float(l1);
            c_s[2*kk+1][0] = __uint_as_float(h2);
            c_s[2*kk+1][1] = __uint_as_float(h3);
            c_s[2*kk+1][2] = __uint_as_float(l2);
            c_s[2*kk+1][3] = __uint_as_float(l3);
        }

        // ---- O += P V (fused 3 passes; np-paired, pass-major) ----
        const uint32_t vB = bB + 2 * KTB;
        #pragma unroll
        for (int kk = 0; kk < 4; kk++) {
            // A fragments, aliased in c_s
            float ph_[4], pl_[4];
            ph_[0] = c_s[2*kk][0];   ph_[1] = c_s[2*kk][1];
            ph_[2] = c_s[2*kk+1][0]; ph_[3] = c_s[2*kk+1][1];
            pl_[0] = c_s[2*kk][2];   pl_[1] = c_s[2*kk][3];
            pl_[2] = c_s[2*kk+1][2]; pl_[3] = c_s[2*kk+1][3];
            #pragma unroll
            for (int np2 = 0; np2 < 4; np2 += 2) {
                uint32_t vh0[4], vh1[4], vl0[4], vl1[4];
                ldmx4(vh0, vB + np2 * 16 * SKB + kk * 32);
                ldmx4(vh1, vB + (np2 + 1) * 16 * SKB + kk * 32);
                ldmx4(vl0, vB + KTB + np2 * 16 * SKB + kk * 32);
                ldmx4(vl1, vB + KTB + (np2 + 1) * 16 * SKB + kk * 32);
                float* a0 = c_o[np2 * 2 + 0];
                float* a1 = c_o[np2 * 2 + 1];
                float* a2 = c_o[np2 * 2 + 2];
                float* a3 = c_o[np2 * 2 + 3];
                mma16816f(a0, ph_, &vh0[0]);
                mma16816f(a1, ph_, &vh0[2]);
                mma16816f(a2, ph_, &vh1[0]);
                mma16816f(a3, ph_, &vh1[2]);
                mma16816f(a0, ph_, &vl0[0]);
                mma16816f(a1, ph_, &vl0[2]);
                mma16816f(a2, ph_, &vl1[0]);
                mma16816f(a3, ph_, &vl1[2]);
                mma16816f(a0, pl_, &vh0[0]);
                mma16816f(a1, pl_, &vh0[2]);
                mma16816f(a2, pl_, &vh1[0]);
                mma16816f(a3, pl_, &vh1[2]);
            }
        }
    }

    // ---- epilogue: O/l -> bf16 hi/lo into g_ah/g_al [b,t,c] ----
    #pragma unroll
    for (int hh = 0; hh < 2; hh++) {
        const float inv = 1.0f / lI[hh];
        const int t = qb * 128 + wid * 16 + g + hh * 8;
        const size_t rowb = ((size_t)bI * TT + t) * CC + hd * 64;
        #pragma unroll
        for (int nt = 0; nt < 8; nt++) {
            const float v0 = c_o[nt][hh * 2 + 0] * inv;
            const float v1 = c_o[nt][hh * 2 + 1] * inv;
            const __nv_bfloat16 h0 = __float2bfloat16(v0);
            const __nv_bfloat16 h1 = __float2bfloat16(v1);
            ushort2 Hu, Lu;
            Hu.x = __bfloat16_as_ushort(h0);
            Hu.y = __bfloat16_as_ushort(h1);
            Lu.x = __bfloat16_as_ushort(__float2bfloat16(v0 - __bfloat162float(h0)));
            Lu.y = __bfloat16_as_ushort(__float2bfloat16(v1 - __bfloat162float(h1)));
            const size_t a0 = rowb + nt * 8 + tig * 2;
            *(ushort2*)&g_ah[a0] = Hu;
            *(ushort2*)&g_al[a0] = Lu;
        }
    }
}

// ---------------------------------------------------------------------------
extern "C" void kernel_launch(void* const* d_in, const int* in_sizes, int n_in,
                              void* d_out, int out_size)
{
    const float* x  = (const float*)d_in[0];
    const float* Wq = (const float*)d_in[1];
    const float* bq = (const float*)d_in[2];
    const float* Wk = (const float*)d_in[3];
    const float* bk = (const float*)d_in[4];
    const float* Wv = (const float*)d_in[5];
    const float* bv = (const float*)d_in[6];
    const float* Wo = (const float*)d_in[7];
    const float* bo = (const float*)d_in[8];
    float* out = (float*)d_out;

    cudaFuncSetAttribute(gemm_tc<0>, cudaFuncAttributeMaxDynamicSharedMemorySize, GEMM_SMEM);
    cudaFuncSetAttribute(gemm_tc<1>, cudaFuncAttributeMaxDynamicSharedMemorySize, GEMM_SMEM);
    cudaFuncSetAttribute(attn_mma,   cudaFuncAttributeMaxDynamicSharedMemorySize, ATT_SMEM);

    __nv_bfloat16 *xh, *xl, *ah, *al;
    cudaGetSymbolAddress((void**)&xh, g_xh);
    cudaGetSymbolAddress((void**)&xl, g_xl);
    cudaGetSymbolAddress((void**)&ah, g_ah);
    cudaGetSymbolAddress((void**)&al, g_al);

    // split x into bf16 hi/lo, transpose+split all weights
    split_f32<<<MMr * CC / 1024, 256>>>((const float4*)x, xh, xl);
    transpose_split_w<<<dim3(32, 32, 4), dim3(32, 8)>>>(Wq, Wk, Wv, Wo);

    // QKV projections (HMMA) -> bf16 hi/lo Q/K/V^T (Q pre-scaled)
    gemm_tc<0><<<dim3(8, 32, 3), 256, GEMM_SMEM>>>(xh, xl, nullptr, bq, bk, bv);

    // attention (HMMA) -> bf16 hi/lo attn output
    attn_mma<<<dim3(16, 32), 256, ATT_SMEM>>>();

    // output projection (HMMA)
    gemm_tc<1><<<dim3(8, 32, 1), 256, GEMM_SMEM>>>(ah, al, out, bo, bo, bo);
}